// round 4
// baseline (speedup 1.0000x reference)
#include <cuda_runtime.h>
#include <cuda_bf16.h>
#include <math.h>
#include <stdint.h>

// Problem constants
#define M_ROWS   8192
#define N_NODES  255
#define K_DIM    2048
#define N_LEAVES 256
#define N_OUT    100
#define N_PEN    127
#define WPAD     256                 // padded W rows

// GEMM tiling: CTA 128x128, BK=64, 8 warps of 64x32
#define BM 128
#define BN 128
#define BK 64
#define NKCHUNK (K_DIM / BK)         // 32
#define SSTRIDE 72                   // bf16 per smem row (64 + 8 pad) = 144 B
#define ROWB    144                  // bytes per smem row
#define TILE_B  (BM * ROWB)          // 18432
#define BUF_B   (4 * TILE_B)         // Ahi,Alo,Bhi,Blo
#define DYN_BYTES (2 * BUF_B)        // 147456

#define NBLK (M_ROWS / 8)            // 1024 tree blocks

// ---------------- scratch (device globals) ----------------------------------
__device__ __nv_bfloat16 g_Xhi[M_ROWS * K_DIM];
__device__ __nv_bfloat16 g_Xlo[M_ROWS * K_DIM];
__device__ __nv_bfloat16 g_Whi[WPAD * K_DIM];
__device__ __nv_bfloat16 g_Wlo[WPAD * K_DIM];
__device__ float g_p[M_ROWS * 256];
__device__ float g_Q[N_LEAVES * N_OUT];
__device__ float g_logQT[N_OUT * N_LEAVES];
__device__ float g_num[N_PEN * NBLK];
__device__ float g_den[N_PEN * NBLK];
__device__ float g_rowloss[NBLK];
__device__ float g_cterm[N_PEN];

// ---------------- helpers ----------------------------------------------------
__device__ __forceinline__ uint32_t smem_u32(const void* p) {
    uint32_t a;
    asm("{ .reg .u64 t; cvta.to.shared.u64 t, %1; cvt.u32.u64 %0, t; }"
        : "=r"(a) : "l"(p));
    return a;
}

__device__ __forceinline__ void mma16816(float* c, const uint32_t* a, const uint32_t* b) {
    asm volatile(
        "mma.sync.aligned.m16n8k16.row.col.f32.bf16.bf16.f32 "
        "{%0,%1,%2,%3}, {%4,%5,%6,%7}, {%8,%9}, {%0,%1,%2,%3};"
        : "+f"(c[0]), "+f"(c[1]), "+f"(c[2]), "+f"(c[3])
        : "r"(a[0]), "r"(a[1]), "r"(a[2]), "r"(a[3]), "r"(b[0]), "r"(b[1]));
}

#define LDSM_X4(r0, r1, r2, r3, addr) \
    asm volatile("ldmatrix.sync.aligned.m8n8.x4.shared.b16 {%0,%1,%2,%3}, [%4];" \
        : "=r"(r0), "=r"(r1), "=r"(r2), "=r"(r3) : "r"(addr))

#define CP_ASYNC16(dst, src) \
    asm volatile("cp.async.cg.shared.global [%0], [%1], 16;" \
        :: "r"(dst), "l"(src) : "memory")
#define CP_COMMIT()  asm volatile("cp.async.commit_group;" ::: "memory")
#define CP_WAIT(n)   asm volatile("cp.async.wait_group %0;" :: "n"(n) : "memory")

// split 4 fp32 -> bf16 hi pair-regs + lo pair-regs
__device__ __forceinline__ void cvt_split4(float4 v, uint32_t* h, uint32_t* l) {
    __nv_bfloat162 h01 = __float22bfloat162_rn(make_float2(v.x, v.y));
    __nv_bfloat162 h23 = __float22bfloat162_rn(make_float2(v.z, v.w));
    float rx = v.x - __bfloat162float(h01.x);
    float ry = v.y - __bfloat162float(h01.y);
    float rz = v.z - __bfloat162float(h23.x);
    float rw = v.w - __bfloat162float(h23.y);
    __nv_bfloat162 l01 = __float22bfloat162_rn(make_float2(rx, ry));
    __nv_bfloat162 l23 = __float22bfloat162_rn(make_float2(rz, rw));
    h[0] = *(uint32_t*)&h01; h[1] = *(uint32_t*)&h23;
    l[0] = *(uint32_t*)&l01; l[1] = *(uint32_t*)&l23;
}

// ---------------- kernel P: fp32 -> bf16 hi/lo pre-conversion ---------------
#define XF4 (M_ROWS * K_DIM / 4)     // 4194304
#define WF4 (WPAD * K_DIM / 4)       // 131072
__global__ __launch_bounds__(256) void convert_kernel(
    const float* __restrict__ X, const float* __restrict__ W)
{
    int idx = blockIdx.x * 256 + threadIdx.x;
    const int total = XF4 + WF4;
    if (idx >= total) return;
    uint32_t h[2], l[2];
    if (idx < XF4) {
        float4 v = ((const float4*)X)[idx];
        cvt_split4(v, h, l);
        ((uint2*)g_Xhi)[idx] = make_uint2(h[0], h[1]);
        ((uint2*)g_Xlo)[idx] = make_uint2(l[0], l[1]);
    } else {
        int wi = idx - XF4;
        int row = wi >> 9;                       // 512 float4 per row
        float4 v = make_float4(0.f, 0.f, 0.f, 0.f);
        if (row < N_NODES) v = ((const float4*)W)[wi];
        cvt_split4(v, h, l);
        ((uint2*)g_Whi)[wi] = make_uint2(h[0], h[1]);
        ((uint2*)g_Wlo)[wi] = make_uint2(l[0], l[1]);
    }
}

// ---------------- kernel 0: log-softmax of leaf params ----------------------
__global__ void softmax_kernel(const float* __restrict__ leaf_params) {
    int l = threadIdx.x;
    if (l >= N_LEAVES) return;
    const float* row = leaf_params + l * N_OUT;
    float mx = -INFINITY;
    for (int o = 0; o < N_OUT; o++) mx = fmaxf(mx, row[o]);
    float s = 0.f;
    for (int o = 0; o < N_OUT; o++) s += expf(row[o] - mx);
    float lse = mx + logf(s);
    for (int o = 0; o < N_OUT; o++) {
        float lq = row[o] - lse;
        g_Q[l * N_OUT + o]        = expf(lq);
        g_logQT[o * N_LEAVES + l] = lq;
    }
}

// ---------------- kernel A: bf16-split HMMA GEMM + sigmoid ------------------
__global__ __launch_bounds__(256, 1) void gemm_mma_kernel(
    const float* __restrict__ bias_g, const float* __restrict__ beta_g)
{
    extern __shared__ __align__(16) char dyn[];
    __shared__ float s_beta[BN], s_bias[BN];

    const int tid  = threadIdx.x;
    const int wid  = tid >> 5;
    const int lane = tid & 31;
    const int m_base = blockIdx.x * BM;
    const int bn     = blockIdx.y * BN;

    if (tid < BN) {
        int col = bn + tid;
        float bt = 0.f, bs = 0.f;
        if (col < N_NODES) { bt = beta_g[col]; bs = bias_g[col]; }
        s_beta[tid] = bt; s_bias[tid] = bs;
    }

    const uint32_t sbase = smem_u32(dyn);

    // loader mapping: seg = tid + it*256; row = seg>>3; c16 = seg&7
    const int lrow = tid >> 3;           // +32 per it
    const int lc16 = tid & 7;

    // global source pointers (bf16), 16B units
    const __nv_bfloat16* Xh = g_Xhi + (size_t)(m_base + lrow) * K_DIM + lc16 * 8;
    const __nv_bfloat16* Xl = g_Xlo + (size_t)(m_base + lrow) * K_DIM + lc16 * 8;
    const __nv_bfloat16* Wh = g_Whi + (size_t)(bn + lrow) * K_DIM + lc16 * 8;
    const __nv_bfloat16* Wl = g_Wlo + (size_t)(bn + lrow) * K_DIM + lc16 * 8;
    const uint32_t dst_off = (uint32_t)(lrow * ROWB + lc16 * 16);

    // compute mapping
    const int wm = wid & 1;
    const int wn = wid >> 1;
    const int g   = lane >> 2;
    const int tig = lane & 3;

    // ldmatrix per-warp base offsets (within a tile)
    const uint32_t lm_row = (uint32_t)(lane & 15);
    const uint32_t lm_khalf = (uint32_t)((lane >> 4) * 16);   // bytes
    const uint32_t a_base = (uint32_t)((wm * 64 + lm_row) * ROWB) + lm_khalf;
    const uint32_t b_base = (uint32_t)((wn * 32 + lm_row) * ROWB) + lm_khalf;

    float acc[4][4][4];
    #pragma unroll
    for (int mi = 0; mi < 4; mi++)
        #pragma unroll
        for (int ni = 0; ni < 4; ni++)
            #pragma unroll
            for (int r = 0; r < 4; r++) acc[mi][ni][r] = 0.f;

    // issue chunk 0
    {
        const uint32_t sb = sbase;
        #pragma unroll
        for (int it = 0; it < 4; it++) {
            uint32_t d = dst_off + it * 32 * ROWB;
            size_t soff = (size_t)(it * 32) * K_DIM;
            CP_ASYNC16(sb + 0 * TILE_B + d, (const char*)(Xh + soff));
            CP_ASYNC16(sb + 1 * TILE_B + d, (const char*)(Xl + soff));
            CP_ASYNC16(sb + 2 * TILE_B + d, (const char*)(Wh + soff));
            CP_ASYNC16(sb + 3 * TILE_B + d, (const char*)(Wl + soff));
        }
        CP_COMMIT();
    }

    for (int kc = 0; kc < NKCHUNK; kc++) {
        const uint32_t sb = sbase + (uint32_t)(kc & 1) * BUF_B;
        if (kc + 1 < NKCHUNK) {
            const uint32_t sn = sbase + (uint32_t)((kc + 1) & 1) * BUF_B;
            const int k0 = (kc + 1) * BK;
            #pragma unroll
            for (int it = 0; it < 4; it++) {
                uint32_t d = dst_off + it * 32 * ROWB;
                size_t soff = (size_t)(it * 32) * K_DIM + k0;
                CP_ASYNC16(sn + 0 * TILE_B + d, (const char*)(Xh + soff));
                CP_ASYNC16(sn + 1 * TILE_B + d, (const char*)(Xl + soff));
                CP_ASYNC16(sn + 2 * TILE_B + d, (const char*)(Wh + soff));
                CP_ASYNC16(sn + 3 * TILE_B + d, (const char*)(Wl + soff));
            }
            CP_COMMIT();
            CP_WAIT(1);
        } else {
            CP_WAIT(0);
        }
        __syncthreads();

        const uint32_t Ahi = sb + 0 * TILE_B, Alo = sb + 1 * TILE_B;
        const uint32_t Bhi = sb + 2 * TILE_B, Blo = sb + 3 * TILE_B;

        #pragma unroll
        for (int ks = 0; ks < 4; ks++) {
            const uint32_t kb = ks * 32;     // byte offset of kstep
            uint32_t ah[4][4], al[4][4], bh[4][2], bl[4][2];
            #pragma unroll
            for (int mi = 0; mi < 4; mi++) {
                uint32_t ao = a_base + mi * 16 * ROWB + kb;
                LDSM_X4(ah[mi][0], ah[mi][1], ah[mi][2], ah[mi][3], Ahi + ao);
                LDSM_X4(al[mi][0], al[mi][1], al[mi][2], al[mi][3], Alo + ao);
            }
            #pragma unroll
            for (int np = 0; np < 2; np++) {
                uint32_t bo = b_base + np * 16 * ROWB + kb;
                uint32_t r0, r1, r2, r3;
                LDSM_X4(r0, r1, r2, r3, Bhi + bo);
                bh[2*np][0] = r0; bh[2*np][1] = r2;
                bh[2*np+1][0] = r1; bh[2*np+1][1] = r3;
                LDSM_X4(r0, r1, r2, r3, Blo + bo);
                bl[2*np][0] = r0; bl[2*np][1] = r2;
                bl[2*np+1][0] = r1; bl[2*np+1][1] = r3;
            }
            #pragma unroll
            for (int mi = 0; mi < 4; mi++)
                #pragma unroll
                for (int ni = 0; ni < 4; ni++) {
                    mma16816(acc[mi][ni], ah[mi], bh[ni]);
                    mma16816(acc[mi][ni], ah[mi], bl[ni]);
                    mma16816(acc[mi][ni], al[mi], bh[ni]);
                }
        }
        __syncthreads();
    }

    // epilogue: sigmoid(beta*(acc+bias)) -> g_p
    #pragma unroll
    for (int mi = 0; mi < 4; mi++) {
        #pragma unroll
        for (int ni = 0; ni < 4; ni++) {
            int rloc = wm * 64 + mi * 16 + g;
            int cloc = wn * 32 + ni * 8 + 2 * tig;
            float bt0 = s_beta[cloc],     bs0 = s_bias[cloc];
            float bt1 = s_beta[cloc + 1], bs1 = s_bias[cloc + 1];
            float z0 = bt0 * (acc[mi][ni][0] + bs0);
            float z1 = bt1 * (acc[mi][ni][1] + bs1);
            float z2 = bt0 * (acc[mi][ni][2] + bs0);
            float z3 = bt1 * (acc[mi][ni][3] + bs1);
            float2 v0 = make_float2(1.f / (1.f + expf(-z0)), 1.f / (1.f + expf(-z1)));
            float2 v1 = make_float2(1.f / (1.f + expf(-z2)), 1.f / (1.f + expf(-z3)));
            size_t base0 = (size_t)(m_base + rloc) * 256 + bn + cloc;
            size_t base1 = (size_t)(m_base + rloc + 8) * 256 + bn + cloc;
            *(float2*)(g_p + base0) = v0;
            *(float2*)(g_p + base1) = v1;
        }
    }
}

// ---------------- kernel B: warp-per-row tree paths + block partials --------
__global__ __launch_bounds__(256) void tree_kernel(
    const int* __restrict__ labels, float* __restrict__ out_output)
{
    __shared__ float sp[8][256];
    __shared__ float snum[N_PEN][8];
    __shared__ float sden[N_PEN][8];
    __shared__ float sloss[8];

    const int tid  = threadIdx.x;
    const int w    = tid >> 5;
    const int lane = tid & 31;
    const int blk  = blockIdx.x;
    const int i    = blk * 8 + w;

    float* spw = sp[w];
    const float* prow = g_p + (size_t)i * 256;
    #pragma unroll
    for (int j = 0; j < 8; j++) {
        int t = lane + j * 32;
        spw[t] = (t < N_NODES) ? prow[t] : 0.f;
    }
    __syncwarp();

    const int label = labels[i];

    float loss = 0.f;
    float best = -1.f;
    int   besti = 0;
    #pragma unroll
    for (int j = 0; j < 8; j++) {
        int t = j * 32 + lane;
        unsigned m = 256u + (unsigned)t;
        float lp = 1.f;
        #pragma unroll
        for (int k = 7; k >= 0; --k) {
            unsigned a  = m >> (k + 1);
            float pa = spw[a - 1];
            lp *= ((m >> k) & 1u) ? pa : (1.f - pa);
        }
        loss += lp * g_logQT[label * N_LEAVES + t];
        if (lp > best) { best = lp; besti = t; }
    }

    #pragma unroll
    for (int o = 16; o > 0; o >>= 1) {
        float v2 = __shfl_xor_sync(0xFFFFFFFFu, best, o);
        int   i2 = __shfl_xor_sync(0xFFFFFFFFu, besti, o);
        if (v2 > best || (v2 == best && i2 < besti)) { best = v2; besti = i2; }
        loss += __shfl_xor_sync(0xFFFFFFFFu, loss, o);
    }
    if (lane == 0) sloss[w] = loss;

    #pragma unroll
    for (int j = 0; j < 4; j++) {
        int t = j * 32 + lane;
        if (t < N_PEN) {
            unsigned m2 = (unsigned)t + 1u;
            int nb = 31 - __clz((int)m2);
            float iv = 1.f;
            for (int k = nb - 1; k >= 0; --k) {
                unsigned a = m2 >> (k + 1);
                float pa = spw[a - 1];
                iv *= ((m2 >> k) & 1u) ? pa : (1.f - pa);
            }
            snum[t][w] = spw[t] * iv;
            sden[t][w] = iv;
        }
    }

    for (int o = lane; o < N_OUT; o += 32)
        out_output[(size_t)i * N_OUT + o] = g_Q[besti * N_OUT + o];

    __syncthreads();

    // block partials
    for (int t = tid; t < N_PEN; t += 256) {
        float sn = 0.f, sd = 0.f;
        #pragma unroll
        for (int r = 0; r < 8; r++) { sn += snum[t][r]; sd += sden[t][r]; }
        g_num[t * NBLK + blk] = sn;
        g_den[t * NBLK + blk] = sd;
    }
    if (tid == 255) {
        float s = 0.f;
        #pragma unroll
        for (int r = 0; r < 8; r++) s += sloss[r];
        g_rowloss[blk] = s;
    }
}

// ---------------- kernel C: reductions over block partials ------------------
__global__ __launch_bounds__(256) void reduce_kernel(float* __restrict__ out)
{
    const int j = blockIdx.x;
    const int t = threadIdx.x;
    __shared__ float s1[256];
    __shared__ float s2[256];

    if (j < N_PEN) {
        const float* num = g_num + (size_t)j * NBLK;
        const float* den = g_den + (size_t)j * NBLK;
        float a = 0.f, d = 0.f;
        for (int r = t; r < NBLK; r += 256) { a += num[r]; d += den[r]; }
        s1[t] = a; s2[t] = d;
        __syncthreads();
        #pragma unroll
        for (int s = 128; s > 0; s >>= 1) {
            if (t < s) { s1[t] += s1[t + s]; s2[t] += s2[t + s]; }
            __syncthreads();
        }
        if (t == 0) {
            float alpha = s1[0] / s2[0];
            int depth = 32 - __clz(j + 1);
            float lm = 0.1f * exp2f(-(float)depth);
            g_cterm[j] = lm * 0.5f * (logf(alpha) + log1pf(-alpha));
        }
    } else {
        float a = 0.f;
        for (int r = t; r < NBLK; r += 256) a += g_rowloss[r];
        s1[t] = a;
        __syncthreads();
        #pragma unroll
        for (int s = 128; s > 0; s >>= 1) {
            if (t < s) s1[t] += s1[t + s];
            __syncthreads();
        }
        if (t == 0) out[0] = -(s1[0] / (float)M_ROWS);
    }
}

// ---------------- kernel D: final C scalar ----------------------------------
__global__ void cfinal_kernel(float* __restrict__ out)
{
    const int t = threadIdx.x;  // 128
    __shared__ float s1[128];
    s1[t] = (t < N_PEN) ? g_cterm[t] : 0.f;
    __syncthreads();
    #pragma unroll
    for (int s = 64; s > 0; s >>= 1) {
        if (t < s) s1[t] += s1[t + s];
        __syncthreads();
    }
    if (t == 0) out[1 + M_ROWS * N_OUT] = -s1[0];
}

// ---------------- entry -----------------------------------------------------
extern "C" void kernel_launch(void* const* d_in, const int* in_sizes, int n_in,
                              void* d_out, int out_size)
{
    const float* x           = (const float*)d_in[0];
    const int*   labels      = (const int*)  d_in[1];
    const float* W           = (const float*)d_in[2];
    const float* b           = (const float*)d_in[3];
    const float* beta        = (const float*)d_in[4];
    const float* leaf_params = (const float*)d_in[5];
    float* out = (float*)d_out;

    cudaFuncSetAttribute(gemm_mma_kernel,
                         cudaFuncAttributeMaxDynamicSharedMemorySize, DYN_BYTES);

    convert_kernel<<<(XF4 + WF4 + 255) / 256, 256>>>(x, W);
    softmax_kernel<<<1, 256>>>(leaf_params);
    dim3 grid(M_ROWS / BM, 256 / BN);
    gemm_mma_kernel<<<grid, 256, DYN_BYTES>>>(b, beta);
    tree_kernel<<<NBLK, 256>>>(labels, out + 1);
    reduce_kernel<<<N_PEN + 1, 256>>>(out);
    cfinal_kernel<<<1, 128>>>(out);
}